// round 5
// baseline (speedup 1.0000x reference)
#include <cuda_runtime.h>
#include <cstdint>

// ---------------------------------------------------------------------------
// ColorHistogramMatchingLoss  (B=8, C=3, 256x256, D_HIST=64)
//
// loss = mean_b sqrt(0.5 * sum_{ch,i,j} (sqrt(Hy/Ty) - sqrt(Hx/Tx))^2)
// H[b,ch,i,j] = sum_n i_y[n] * rbf(u[n],c_i) * rbf(v[n],c_j)
// rbf(d,c) = 1 / (1 + ((d-c)/0.02)^2),  centers = linspace(-3,3,64)
// ---------------------------------------------------------------------------

#define NPIX        65536
#define BATCH       8
#define NUNITS      48             // 2 imgs * 8 batch * 3 ch
#define SPLITS      32
#define PIX_SPLIT   2048           // NPIX / SPLITS
#define CHUNK       64
#define NCHUNK      32             // PIX_SPLIT / CHUNK

// scaled: t = 50*u - 50*c_k ;  50*c_k = k*(300/63) - 150
#define CK_STEP     (300.0f / 63.0f)

// -------------------------------- scratch ----------------------------------
__device__ float g_part[NUNITS * SPLITS * 4096];   // per-split partial hists
__device__ float g_hist[NUNITS * 4096];            // reduced hists
__device__ float g_hb  [BATCH];                    // per-batch h_norm

// ---------------------------- kernel 1: histogram --------------------------
// Block: 128 threads.
// Phase A (pixel-parallel): thread t owns pixel p = t&63, role = t>>6
//   (0 -> U weights incl. iy factor, 1 -> V weights). Loads rgb from GMEM
//   (prefetched one chunk ahead), computes 64 RBF weights, stores to SMEM.
// Phase B (GEMM): 2 groups of 64 threads; each thread owns an 8x8 tile of
//   the 64x64 histogram as f32x2 accumulators (lanes = pixel parity).
//
// SMEM weight layout (per role): rows of 512B, one per pixel-pair pp.
//   logical: [pp][k=64][par=2] f32.  16B units permuted: unit(k) = q*8 + r
//   where r = k>>3, q = (k>>1)&3.  Unit holds k = {8r+2q, 8r+2q+1} x par.
//   -> Phase-B loads at byte (pp*512 + q*128 + r*16): bank-group == r (or c)
//      => conflict-free.  Phase-A STS with k-rotation (j + 8*pp) => 2-way max.

#define FMA2(d, a, b) \
    asm("fma.rn.f32x2 %0, %1, %2, %0;" : "+l"(d) : "l"(a), "l"(b))

__device__ __forceinline__ float pair_sum(unsigned long long a) {
    return __uint_as_float((unsigned)a) + __uint_as_float((unsigned)(a >> 32));
}

__global__ __launch_bounds__(128) void hist_kernel(const float* __restrict__ x,
                                                   const float* __restrict__ y) {
    __shared__ __align__(16) float s_U[32 * 128];   // 16 KB
    __shared__ __align__(16) float s_V[32 * 128];   // 16 KB

    const int tid   = threadIdx.x;
    const int bx    = blockIdx.x;
    const int split = bx & (SPLITS - 1);
    const int unit  = bx >> 5;                       // 0..47
    const int img   = unit / 24;
    const int rem   = unit - img * 24;
    const int b     = rem / 3;
    const int ch    = rem - b * 3;

    const float* __restrict__ base =
        (img ? y : x) + b * (3 * NPIX) + split * PIX_SPLIT;

    // ---- phase-A identity ----
    const int role = tid >> 6;                       // 0 = U, 1 = V
    const int p    = tid & 63;                       // pixel within chunk
    const int pp   = p >> 1;
    const int par  = p & 1;

    // (U,V) = linear combos of (su,sv):
    // ch0: U=su      V=sv      ch1: U=-su  V=sv-su    ch2: U=-sv  V=su-sv
    float ca, cb;
    if (role == 0) {
        ca = (ch == 0) ? 1.0f : (ch == 1) ? -1.0f : 0.0f;
        cb = (ch == 2) ? -1.0f : 0.0f;
    } else {
        ca = (ch == 0) ? 0.0f : (ch == 1) ? -1.0f : 1.0f;
        cb = (ch == 2) ? -1.0f : 1.0f;
    }
    float* __restrict__ srow = (role ? s_V : s_U) + pp * 128;
    const int k0 = (8 * pp) & 63;                    // STS bank rotation

    // ---- phase-B identity ----
    const int group = tid >> 6;                      // pp halves
    const int g     = tid & 63;
    const int r     = g >> 3;                        // row block
    const int c     = g & 7;                         // col block

    unsigned long long acc[8][8];
#pragma unroll
    for (int i = 0; i < 8; ++i)
#pragma unroll
        for (int j = 0; j < 8; ++j) acc[i][j] = 0ull;

    // prefetch chunk 0 rgb
    float rr = base[p], gg = base[NPIX + p], bb = base[2 * NPIX + p];

    for (int chnk = 0; chnk < NCHUNK; ++chnk) {
        // ---------------- phase A: weight generation ----------------
        float rv = rr + 1e-6f, gv = gg + 1e-6f, blv = bb + 1e-6f;
        float lr = __logf(rv), lg = __logf(gv), lb = __logf(blv);
        float su = (lr - lg) * 50.0f;
        float sv = (lr - lb) * 50.0f;
        float wnum = 1.0f;
        if (role == 0)
            wnum = sqrtf(fmaf(rv, rv, fmaf(gv, gv, blv * blv)));
        float a150 = fmaf(ca, su, cb * sv) + 150.0f;

#pragma unroll 8
        for (int j = 0; j < 64; ++j) {
            int   k = (j + k0) & 63;
            float d = fmaf(-(float)k, CK_STEP, a150);
            float q = fmaf(d, d, 1.0f);
            float w = __fdividef(wnum, q);
            // permuted unit: ((k>>1)&3)*8 + (k>>3); intra: 2*(k&1)+par
            int word = (((((k >> 1) & 3) << 3) | (k >> 3)) << 2)
                     + ((k & 1) << 1) + par;
            srow[word] = w;
        }

        // prefetch next chunk rgb (latency hidden under phase B)
        if (chnk + 1 < NCHUNK) {
            int np = (chnk + 1) * CHUNK + p;
            rr = base[np]; gg = base[NPIX + np]; bb = base[2 * NPIX + np];
        }
        __syncthreads();

        // ---------------- phase B: outer-product updates ----------------
        const char* bu = (const char*)s_U + r * 16;
        const char* bv = (const char*)s_V + c * 16;
#pragma unroll 1
        for (int q = 0; q < 16; ++q) {
            const int  ppi = (group << 4) + q;
            const char* up = bu + ppi * 512;
            const char* vp = bv + ppi * 512;
            ulonglong2 U0 = *(const ulonglong2*)(up);
            ulonglong2 U1 = *(const ulonglong2*)(up + 128);
            ulonglong2 U2 = *(const ulonglong2*)(up + 256);
            ulonglong2 U3 = *(const ulonglong2*)(up + 384);
            ulonglong2 V0 = *(const ulonglong2*)(vp);
            ulonglong2 V1 = *(const ulonglong2*)(vp + 128);
            ulonglong2 V2 = *(const ulonglong2*)(vp + 256);
            ulonglong2 V3 = *(const ulonglong2*)(vp + 384);
            unsigned long long u[8] = {U0.x, U0.y, U1.x, U1.y,
                                       U2.x, U2.y, U3.x, U3.y};
            unsigned long long v[8] = {V0.x, V0.y, V1.x, V1.y,
                                       V2.x, V2.y, V3.x, V3.y};
#pragma unroll
            for (int i = 0; i < 8; ++i)
#pragma unroll
                for (int jj = 0; jj < 8; ++jj) FMA2(acc[i][jj], u[i], v[jj]);
        }
        __syncthreads();   // protect s_U/s_V before next phase A
    }

    // ---- combine both groups in smem, write partial histogram ----
    float* s_h = s_U;
    if (group == 0) {
#pragma unroll
        for (int i = 0; i < 8; ++i)
#pragma unroll
            for (int j = 0; j < 8; ++j)
                s_h[(r * 8 + i) * 64 + c * 8 + j] = pair_sum(acc[i][j]);
    }
    __syncthreads();
    if (group == 1) {
#pragma unroll
        for (int i = 0; i < 8; ++i)
#pragma unroll
            for (int j = 0; j < 8; ++j)
                s_h[(r * 8 + i) * 64 + c * 8 + j] += pair_sum(acc[i][j]);
    }
    __syncthreads();

    float* out = g_part + bx * 4096;
    for (int i = tid; i < 4096; i += 128) out[i] = s_h[i];
}

// ------------------------- kernel 2: reduce splits -------------------------
__global__ void reduce_splits_kernel() {
    int cid = blockIdx.x * 256 + threadIdx.x;        // < 48*4096
    int u   = cid >> 12;
    int cc  = cid & 4095;
    float s = 0.0f;
#pragma unroll 8
    for (int sp = 0; sp < SPLITS; ++sp)
        s += g_part[(u * SPLITS + sp) * 4096 + cc];
    g_hist[cid] = s;
}

// ------------------------- kernel 3: per-batch loss ------------------------
__device__ __forceinline__ float block_reduce(float v) {
    __shared__ float sb[8];
    int tid = threadIdx.x;
#pragma unroll
    for (int o = 16; o > 0; o >>= 1) v += __shfl_down_sync(0xffffffffu, v, o);
    if ((tid & 31) == 0) sb[tid >> 5] = v;
    __syncthreads();
    if (tid < 32) {
        v = (tid < 8) ? sb[tid] : 0.0f;
#pragma unroll
        for (int o = 4; o > 0; o >>= 1) v += __shfl_down_sync(0xffffffffu, v, o);
        if (tid == 0) sb[0] = v;
    }
    __syncthreads();
    v = sb[0];
    __syncthreads();
    return v;
}

__global__ void finalize_kernel() {
    const int b   = blockIdx.x;
    const int tid = threadIdx.x;
    const float* __restrict__ xh = g_hist + (b * 3) * 4096;        // img 0
    const float* __restrict__ yh = g_hist + (24 + b * 3) * 4096;   // img 1

    float tx = 0.0f, ty = 0.0f;
    for (int i = tid; i < 3 * 4096; i += 256) { tx += xh[i]; ty += yh[i]; }
    tx = block_reduce(tx);
    ty = block_reduce(ty);
    float sx = rsqrtf(tx), sy = rsqrtf(ty);

    float h = 0.0f;
    for (int i = tid; i < 3 * 4096; i += 256) {
        float d = sqrtf(yh[i]) * sy - sqrtf(xh[i]) * sx;
        h = fmaf(d, d, h);
    }
    h = block_reduce(h);
    if (tid == 0) g_hb[b] = sqrtf(h * 0.5f);
}

// --------------------------- kernel 4: final mean --------------------------
__global__ void mean_kernel(float* __restrict__ out) {
    if (threadIdx.x == 0) {
        float s = 0.0f;
#pragma unroll
        for (int i = 0; i < BATCH; ++i) s += g_hb[i];
        out[0] = s * (1.0f / BATCH);
    }
}

// ----------------------- no-op (ncu -s alignment) --------------------------
__global__ void noop_kernel() {}

// ------------------------------- entry point -------------------------------
extern "C" void kernel_launch(void* const* d_in, const int* in_sizes, int n_in,
                              void* d_out, int out_size) {
    const float* x = (const float*)d_in[0];
    const float* y = (const float*)d_in[1];
    float* out = (float*)d_out;

    hist_kernel<<<NUNITS * SPLITS, 128>>>(x, y);            // launch idx 0 (mod 5)
    reduce_splits_kernel<<<(NUNITS * 4096) / 256, 256>>>();
    finalize_kernel<<<BATCH, 256>>>();
    mean_kernel<<<1, 32>>>(out);
    noop_kernel<<<1, 32>>>();   // pads to 5 launches/call -> idx 5 == hist
}